// round 1
// baseline (speedup 1.0000x reference)
#include <cuda_runtime.h>
#include <stdint.h>

// AUC over sigmoid(output) with 30 uniform thresholds.
// Phase 1: 31-bin histogram of bin = floor(30*sigmoid(x)) over all 32M elems
//          (hist_all) + same for the one true-class element per row (hist_t).
// Phase 2: tiny cumsum/trapezoid -> scalar.
//
// Hot path per element: FMUL, EX2, FADD, RCP, FFMA, FADD(magic), IMAD,
// LDS, IADD, STS  -> ~10 lane-inst, 2 MUFU, 2 shared ops. HBM-bound.

#define NROWS   500000
#define NCOLS   64
#define NELEM   (NROWS * NCOLS)        // 32,000,000
#define NF4     (NELEM / 4)            // 8,000,000
#define NBINS   31
#define BLOCK   384
#define GRID    444                    // 3 blocks/SM on 148 SMs

__device__ unsigned int g_hist_all[32];
__device__ unsigned int g_hist_t[32];

__global__ void zero_kernel() {
    int t = threadIdx.x;
    if (t < 32) { g_hist_all[t] = 0u; g_hist_t[t] = 0u; }
}

// bin = floor(30 * sigmoid(x)), exact except in ~1-ulp windows around bin
// boundaries (negligible effect on the final scalar).
__device__ __forceinline__ int bin_of(float x) {
    float t = x * -1.4426950408889634f;          // -x * log2(e)
    float e;
    asm("ex2.approx.f32 %0, %1;" : "=f"(e) : "f"(t));   // e^-x
    float d = e + 1.0f;                           // d >= 1.0
    float v;
    asm("rcp.approx.f32 %0, %1;" : "=f"(v) : "f"(d));   // sigmoid, in (0, 1]
    float z = fmaf(v, 30.0f, -0.5f);              // v*30 - 0.5  in (-0.5, 29.5]
    float y = z + 12582912.0f;                    // + 1.5*2^23: RN -> floor(v*30)
    return __float_as_int(y) - 0x4B400000;        // 0..30
}

__global__ __launch_bounds__(BLOCK, 3)
void hist_kernel(const float4* __restrict__ o4, const int* __restrict__ tgt) {
    // Per-thread private histogram: hist[bin*BLOCK + tid].
    // Bank = tid % 32 for every bin -> conflict-free, no atomics.
    __shared__ unsigned int hist[NBINS * BLOCK];   // 47,616 B (static, <48KB)
    __shared__ unsigned int strue[32];

    const int tid = threadIdx.x;
    #pragma unroll 4
    for (int i = tid; i < NBINS * BLOCK; i += BLOCK) hist[i] = 0u;
    if (tid < 32) strue[tid] = 0u;
    __syncthreads();

    const int stride = gridDim.x * BLOCK;
    for (int f = blockIdx.x * BLOCK + tid; f < NF4; f += stride) {
        float4 x = __ldg(o4 + f);
        int tg = __ldg(tgt + (f >> 4));            // 16 float4s per row

        int b0 = bin_of(x.x);
        int b1 = bin_of(x.y);
        int b2 = bin_of(x.z);
        int b3 = bin_of(x.w);

        hist[b0 * BLOCK + tid]++;
        hist[b1 * BLOCK + tid]++;
        hist[b2 * BLOCK + tid]++;
        hist[b3 * BLOCK + tid]++;

        // True-class element: column tgt of this row; 1 in 16 threads matches.
        if ((tg >> 2) == (f & 15)) {
            int j = tg & 3;
            int bb = (j & 2) ? ((j & 1) ? b3 : b2) : ((j & 1) ? b1 : b0);
            atomicAdd(&strue[bb], 1u);
        }
    }
    __syncthreads();

    // Block reduction of private histograms -> global atomics (31 per block).
    int lane = tid & 31, wid = tid >> 5;           // 12 warps
    for (int b = wid; b < NBINS; b += (BLOCK / 32)) {
        unsigned s = 0;
        #pragma unroll
        for (int k = 0; k < BLOCK / 32; k++) s += hist[b * BLOCK + k * 32 + lane];
        #pragma unroll
        for (int o = 16; o; o >>= 1) s += __shfl_down_sync(0xffffffffu, s, o);
        if (lane == 0 && s) atomicAdd(&g_hist_all[b], s);
    }
    if (tid < NBINS) {
        unsigned s = strue[tid];
        if (s) atomicAdd(&g_hist_t[tid], s);
    }
}

__global__ void finalize_kernel(float* __restrict__ out) {
    if (threadIdx.x != 0 || blockIdx.x != 0) return;
    double ht[NBINS], ha[NBINS];
    double trues = 0.0;
    const double total = (double)NELEM;
    for (int i = 0; i < NBINS; i++) {
        ht[i] = (double)g_hist_t[i];
        ha[i] = (double)g_hist_all[i];
        trues += ht[i];
    }
    double falses = total - trues;

    // tp_asc[j] = trues - cumsum(hist_t)[0..j],  j = 0..29 (ascending bins)
    double tp_asc[30], fp_asc[30];
    double ct = 0.0, cf = 0.0;
    for (int j = 0; j < 30; j++) {
        ct += ht[j];
        cf += (ha[j] - ht[j]);
        tp_asc[j] = trues  - ct;
        fp_asc[j] = falses - cf;
    }

    const double eps = 1e-8;
    double area = 0.0, pt = 0.0, pf = 0.0;   // leading zero point
    for (int i = 0; i < 30; i++) {
        double tpr = tp_asc[29 - i] / (trues  + eps);
        double fpr = fp_asc[29 - i] / (falses + eps);
        double w  = fabs(fpr - pf);
        double mn = fmin(tpr, pt), mx = fmax(tpr, pt);
        area += w * mn + 0.5 * w * (mx - mn);
        pt = tpr; pf = fpr;
    }
    out[0] = (float)area;
}

extern "C" void kernel_launch(void* const* d_in, const int* in_sizes, int n_in,
                              void* d_out, int out_size) {
    const float* output = (const float*)d_in[0];
    const int*   target = (const int*)d_in[1];
    // Defensive: identify by size in case metadata order differs.
    if (n_in >= 2 && in_sizes[0] == NROWS && in_sizes[1] == NELEM) {
        output = (const float*)d_in[1];
        target = (const int*)d_in[0];
    }

    zero_kernel<<<1, 32>>>();
    hist_kernel<<<GRID, BLOCK>>>((const float4*)output, target);
    finalize_kernel<<<1, 1>>>((float*)d_out);
}